// round 14
// baseline (speedup 1.0000x reference)
#include <cuda_runtime.h>
#include <cuda_fp16.h>
#include <cstdint>

#define BB 256
#define NTOK 63
#define DD 128
#define EE 8
#define HH 256
#define T2 160

// ---------------- device globals ----------------
__device__ float g_gates[BB * 2];
__device__ int   g_eidx[BB * 2];
__device__ __half W1T[EE * HH * DD];     // [e][hcol][d] k-contig, fp16
__device__ __half W2T[EE * 4 * T2 * 64]; // [e][kchunk][o][64], fp16

// ---------------- smem layout (bytes) ----------------
#define SM_X    0                     // x: 64 rows x 256B (swz)
#define SM_H    16384                 // h chunk: 64 rows x 128B (swz)
#define SM_B1   24576                 // W1 chunk: 2 bufs x 16384 (swz)
#define SM_B2   57344                 // W2 chunk: 2 bufs x 20480 (160 rows x 128B, swz)
#define B2SZ    20480
#define SM_BIAS 98304                 // 160 floats (combined out bias)
#define SM_BIAS1 98944                // 512 floats (b1 for e0,e1)
#define SM_TOT  100992

// ---------------- PTX helpers ----------------
__device__ __forceinline__ uint32_t smem_u32(const void* p) {
    uint32_t a;
    asm("{ .reg .u64 t; cvta.to.shared.u64 t, %1; cvt.u32.u64 %0, t; }" : "=r"(a) : "l"(p));
    return a;
}
__device__ __forceinline__ void ldsm4(uint32_t* r, uint32_t addr) {
    asm volatile("ldmatrix.sync.aligned.m8n8.x4.shared.b16 {%0,%1,%2,%3}, [%4];"
        : "=r"(r[0]), "=r"(r[1]), "=r"(r[2]), "=r"(r[3]) : "r"(addr));
}
__device__ __forceinline__ void ldsm2(uint32_t* r, uint32_t addr) {
    asm volatile("ldmatrix.sync.aligned.m8n8.x2.shared.b16 {%0,%1}, [%2];"
        : "=r"(r[0]), "=r"(r[1]) : "r"(addr));
}
__device__ __forceinline__ void mma16(float* d, const uint32_t* a, uint32_t b0, uint32_t b1) {
    asm volatile("mma.sync.aligned.m16n8k16.row.col.f32.f16.f16.f32 "
        "{%0,%1,%2,%3}, {%4,%5,%6,%7}, {%8,%9}, {%0,%1,%2,%3};"
        : "+f"(d[0]), "+f"(d[1]), "+f"(d[2]), "+f"(d[3])
        : "r"(a[0]), "r"(a[1]), "r"(a[2]), "r"(a[3]), "r"(b0), "r"(b1));
}
__device__ __forceinline__ void cp16(uint32_t dst, const void* src) {
    asm volatile("cp.async.cg.shared.global [%0], [%1], 16;" :: "r"(dst), "l"(src));
}
#define CP_COMMIT() asm volatile("cp.async.commit_group;" ::: "memory")
#define CP_WAIT(n)  asm volatile("cp.async.wait_group %0;" :: "n"(n) : "memory")

// ---------------- prep: transpose + fp16 convert + fused router ----------------
__global__ void prep_w(const float* __restrict__ w1, const float* __restrict__ w2,
                       const float* __restrict__ x,  const float* __restrict__ rw,
                       const float* __restrict__ rb) {
    __shared__ float t[32][33];
    __shared__ float pooled[DD];
    __shared__ float logits[EE];
    int e = blockIdx.z, bx = blockIdx.x;
    int tx = threadIdx.x, ty = threadIdx.y;
    int tid = ty * 32 + tx;
    if (bx < 32) {
        int d0 = (bx & 3) * 32, h0 = (bx >> 2) * 32;
        #pragma unroll
        for (int i = 0; i < 4; i++)
            t[ty + 8 * i][tx] = w1[(e * DD + d0 + ty + 8 * i) * HH + h0 + tx];
        __syncthreads();
        #pragma unroll
        for (int i = 0; i < 4; i++)
            W1T[(e * HH + h0 + ty + 8 * i) * DD + d0 + tx] =
                __float2half_rn(t[tx][ty + 8 * i]);
    } else if (bx < 72) {
        int i2 = bx - 32;
        int k0 = (i2 & 7) * 32, o0 = (i2 >> 3) * 32;
        #pragma unroll
        for (int i = 0; i < 4; i++)
            t[ty + 8 * i][tx] = w2[(e * HH + k0 + ty + 8 * i) * T2 + o0 + tx];
        __syncthreads();
        #pragma unroll
        for (int i = 0; i < 4; i++) {
            int hd = k0 + tx, o = o0 + ty + 8 * i;
            W2T[((e * 4 + (hd >> 6)) * T2 + o) * 64 + (hd & 63)] =
                __float2half_rn(t[tx][ty + 8 * i]);
        }
    } else {
        // router for batch b
        int b = (bx - 72) * 8 + e;
        const float* xb = x + b * 64 * DD;
        if (tid < DD) {
            float s = 0.f;
            #pragma unroll 4
            for (int n = 1; n < 64; n++) s += xb[n * DD + tid];
            pooled[tid] = s * (1.0f / 63.0f);
        }
        __syncthreads();
        if (tid < EE) {
            float l = rb[tid];
            #pragma unroll 4
            for (int dd = 0; dd < DD; dd++) l += pooled[dd] * rw[dd * EE + tid];
            logits[tid] = l;
        }
        __syncthreads();
        if (tid == 0) {
            float mx = logits[0];
            #pragma unroll
            for (int k = 1; k < EE; k++) mx = fmaxf(mx, logits[k]);
            float p[EE];
            float se = 0.f;
            #pragma unroll
            for (int k = 0; k < EE; k++) { p[k] = expf(logits[k] - mx); se += p[k]; }
            int i1 = 0;
            #pragma unroll
            for (int k = 1; k < EE; k++) if (p[k] > p[i1]) i1 = k;
            int i2 = (i1 == 0) ? 1 : 0;
            #pragma unroll
            for (int k = 0; k < EE; k++) if (k != i1 && p[k] > p[i2]) i2 = k;
            float inv = 1.f / se;
            g_eidx[b * 2 + 0]  = i1;
            g_gates[b * 2 + 0] = p[i1] * inv;
            g_eidx[b * 2 + 1]  = i2;
            g_gates[b * 2 + 1] = p[i2] * inv;
        }
    }
}

// ---------------- cp.async tile loaders (over-range calls are empty) ----------------
__device__ __forceinline__ void load_b1t(uint32_t sb, int ch, int e0, int e1, int tid) {
    if (ch >= 8) return;
    int e = (ch >> 2) ? e1 : e0;
    const char* s = (const char*)(W1T + (e * HH + (ch & 3) * 64) * DD);
    uint32_t dst = sb + SM_B1 + (uint32_t)(ch & 1) * 16384;
    #pragma unroll
    for (int i = 0; i < 4; i++) {
        int c = tid + i * 256;
        int row = c >> 4, seg = c & 15;
        uint32_t d = (uint32_t)row * 256 + (uint32_t)((seg ^ (row & 7)) << 4);
        cp16(dst + d, s + c * 16);
    }
}
// full 64-col W2 chunk: 160 rows x 128B, swizzled (8 segs/row)
__device__ __forceinline__ void load_b2t(uint32_t sb, int ch, int e0, int e1, int tid) {
    if (ch >= 8) return;
    int e = (ch >> 2) ? e1 : e0;
    const char* s = (const char*)(W2T + (e * 4 + (ch & 3)) * T2 * 64);
    uint32_t buf = sb + SM_B2 + (uint32_t)(ch & 1) * B2SZ;
    #pragma unroll
    for (int i = 0; i < 5; i++) {
        int c = tid + i * 256;  // 1280 copies
        int row = c >> 3, seg = c & 7;
        uint32_t d = (uint32_t)row * 128 + (uint32_t)((seg ^ (row & 7)) << 4);
        cp16(buf + d, s + row * 128 + seg * 16);
    }
}

// ---------------- main fused kernel ----------------
__global__ __launch_bounds__(256, 2) void moe_kernel(
    const float* __restrict__ x,
    const float* __restrict__ b1g,
    const float* __restrict__ b2g,
    float* __restrict__ out) {
    extern __shared__ char smem[];
    uint32_t sb = smem_u32(smem);
    int tid = threadIdx.x, wid = tid >> 5, lane = tid & 31;
    int b = blockIdx.x;
    const int wm = wid & 3, wn = wid >> 2;       // GEMM1 grid 4m x 2n
    const int wm2 = wid >> 2, wn2 = wid & 3;     // GEMM2 grid 2m x 4n
    const int t = lane >> 3, r8 = lane & 7, q = lane >> 2, p2 = (lane & 3) * 2;

    const int e0 = g_eidx[b * 2 + 0], e1 = g_eidx[b * 2 + 1];
    const float gt0 = g_gates[b * 2 + 0], gt1 = g_gates[b * 2 + 1];

    if (tid < T2)
        ((float*)(smem + SM_BIAS))[tid] =
            gt0 * __ldg(b2g + e0 * T2 + tid) + gt1 * __ldg(b2g + e1 * T2 + tid);
    // stage b1 for both experts
    {
        float* bc1 = (float*)(smem + SM_BIAS1);
        bc1[tid]       = __ldg(b1g + e0 * HH + tid);
        bc1[256 + tid] = __ldg(b1g + e1 * HH + tid);
    }

    // zero x row 63
    if (tid < 16) {
        uint32_t off = 63u * 256 + (uint32_t)((tid ^ 7) << 4);
        *(uint4*)(smem + SM_X + off) = make_uint4(0, 0, 0, 0);
    }
    // fill x rows 0..62, fp16, swizzled
    if (tid < 252) {
        int r = tid >> 2, seg32 = (tid & 3) * 32;
        const float4* xr = (const float4*)(x + (b * 64 + 1 + r) * DD + seg32);
        #pragma unroll
        for (int j = 0; j < 8; j++) {
            float4 v = xr[j];
            int d = seg32 + j * 4;
            __half2 h01 = __floats2half2_rn(v.x, v.y);
            __half2 h23 = __floats2half2_rn(v.z, v.w);
            uint32_t off = (uint32_t)r * 256 + (uint32_t)((((d >> 3) ^ (r & 7)) << 4) + ((d * 2) & 15));
            *(__half2*)(smem + SM_X + off)     = h01;
            *(__half2*)(smem + SM_X + off + 4) = h23;
        }
    }
    __syncthreads();

    // prologue commit order: [B1(0)] [B2(0)] [B1(1)]
    load_b1t(sb, 0, e0, e1, tid);  CP_COMMIT();
    load_b2t(sb, 0, e0, e1, tid);  CP_COMMIT();
    load_b1t(sb, 1, e0, e1, tid);  CP_COMMIT();

    // GEMM1 per-lane bases
    const int rA = wm * 16 + (t & 1) * 8 + r8;
    const uint32_t xbase = sb + SM_X + (uint32_t)rA * 256;
    const int rB0 = wn * 32 + (t >> 1) * 8 + r8;
    // GEMM2 per-lane bases
    const uint32_t hb2_0 = sb + SM_H + (uint32_t)(wm2 * 32 + (t & 1) * 8 + r8) * 128;
    const uint32_t hb2_1 = hb2_0 + 16 * 128;
    const int rW = wn2 * 40 + (t >> 1) * 8 + r8;     // B2 n-tiles {0,1}; +16 -> {2,3}
    const int rX = wn2 * 40 + 32 + r8;               // B2 n-tile 4 (ldsm.x2, lanes 0-15)

    // ---- x A-fragments: loaded once, reused across all 8 chunks ----
    uint32_t xf[32];
    #pragma unroll
    for (int ks = 0; ks < 8; ks++) {
        uint32_t sa = (uint32_t)(((2 * ks + (t >> 1)) ^ r8) << 4);
        ldsm4(xf + 4 * ks, xbase + sa);
    }

    float acc2[2][5][4];
    #pragma unroll
    for (int mt = 0; mt < 2; mt++)
        #pragma unroll
        for (int nt = 0; nt < 5; nt++)
            #pragma unroll
            for (int j = 0; j < 4; j++) acc2[mt][nt][j] = 0.f;

    const float* bc1 = (const float*)(smem + SM_BIAS1);

    for (int ch = 0; ch < 8; ch++) {
        const float g  = (ch >> 2) ? gt1 : gt0;
        const int   c4 = ch & 3;

        // ---- sync#1: B1(ch) ready (oldest pending); H free ----
        CP_WAIT(2);
        __syncthreads();

        uint32_t b1base = sb + SM_B1 + (uint32_t)(ch & 1) * 16384;
        // two independent ntp passes: acc1 live range halved, epilogue overlaps
        #pragma unroll
        for (int ntp = 0; ntp < 2; ntp++) {
            float acc1[2][4];
            #pragma unroll
            for (int nt = 0; nt < 2; nt++)
                #pragma unroll
                for (int j = 0; j < 4; j++) acc1[nt][j] = 0.f;

            int rB = rB0 + ntp * 16;
            uint32_t bb = b1base + (uint32_t)rB * 256;
            int bx7 = rB & 7;
            #pragma unroll
            for (int ks = 0; ks < 8; ks++) {
                uint32_t a = bb + (uint32_t)(((2 * ks + (t & 1)) ^ bx7) << 4);
                uint32_t bh[4];
                ldsm4(bh, a);
                mma16(acc1[0], xf + 4 * ks, bh[0], bh[1]);
                mma16(acc1[1], xf + 4 * ks, bh[2], bh[3]);
            }
            // partial h epilogue: bias + relu + gate -> fp16 (swizzled)
            #pragma unroll
            for (int nt = 0; nt < 2; nt++) {
                int col = wn * 32 + (ntp * 2 + nt) * 8 + p2;
                float bv0 = bc1[(ch >> 2) * 256 + c4 * 64 + col];
                float bv1 = bc1[(ch >> 2) * 256 + c4 * 64 + col + 1];
                int r0 = wm * 16 + q, r1 = r0 + 8;
                float v00 = g * fmaxf(acc1[nt][0] + bv0, 0.f);
                float v01 = g * fmaxf(acc1[nt][1] + bv1, 0.f);
                float v10 = g * fmaxf(acc1[nt][2] + bv0, 0.f);
                float v11 = g * fmaxf(acc1[nt][3] + bv1, 0.f);
                uint32_t o0 = (uint32_t)r0 * 128 + (uint32_t)((((col >> 3) ^ (r0 & 7)) << 4) + ((col * 2) & 15));
                uint32_t o1 = (uint32_t)r1 * 128 + (uint32_t)((((col >> 3) ^ (r1 & 7)) << 4) + ((col * 2) & 15));
                *(__half2*)(smem + SM_H + o0) = __floats2half2_rn(v00, v01);
                *(__half2*)(smem + SM_H + o1) = __floats2half2_rn(v10, v11);
            }
        }

        // ---- sync#2: B2(ch) ready; H visible; buffers free for refill ----
        CP_WAIT(1);
        __syncthreads();
        load_b2t(sb, ch + 1, e0, e1, tid); CP_COMMIT();
        load_b1t(sb, ch + 2, e0, e1, tid); CP_COMMIT();

        // ---- GEMM2: full 64-k chunk, 2m x 4n warp tiles ----
        uint32_t b2base = sb + SM_B2 + (uint32_t)(ch & 1) * B2SZ;
        #pragma unroll
        for (int kt = 0; kt < 4; kt++) {
            uint32_t sa = (uint32_t)(((kt * 2 + (t >> 1)) ^ r8) << 4);
            uint32_t ah0[4], ah1[4];
            ldsm4(ah0, hb2_0 + sa);
            ldsm4(ah1, hb2_1 + sa);
            uint32_t bseg = (uint32_t)(((kt * 2 + (t & 1)) ^ r8) << 4);
            uint32_t b01[4], b23[4], b4[2];
            ldsm4(b01, b2base + (uint32_t)rW * 128 + bseg);
            ldsm4(b23, b2base + (uint32_t)(rW + 16) * 128 + bseg);
            ldsm2(b4,  b2base + (uint32_t)rX * 128 + (uint32_t)(((kt * 2 + t) ^ r8) << 4));
            mma16(acc2[0][0], ah0, b01[0], b01[1]);
            mma16(acc2[1][0], ah1, b01[0], b01[1]);
            mma16(acc2[0][1], ah0, b01[2], b01[3]);
            mma16(acc2[1][1], ah1, b01[2], b01[3]);
            mma16(acc2[0][2], ah0, b23[0], b23[1]);
            mma16(acc2[1][2], ah1, b23[0], b23[1]);
            mma16(acc2[0][3], ah0, b23[2], b23[3]);
            mma16(acc2[1][3], ah1, b23[2], b23[3]);
            mma16(acc2[0][4], ah0, b4[0], b4[1]);
            mma16(acc2[1][4], ah1, b4[0], b4[1]);
        }
    }

    // ---- final epilogue: combined bias + store (GEMM2 grid indices) ----
    const float* bc = (const float*)(smem + SM_BIAS);
    #pragma unroll
    for (int mt = 0; mt < 2; mt++) {
        int r0 = wm2 * 32 + mt * 16 + q;
        #pragma unroll
        for (int nt = 0; nt < 5; nt++) {
            int col = wn2 * 40 + nt * 8 + p2;
            float bv0 = bc[col], bv1 = bc[col + 1];
            if (r0 < NTOK) {
                float2 v = make_float2(acc2[mt][nt][0] + bv0, acc2[mt][nt][1] + bv1);
                *(float2*)(out + (b * NTOK + r0) * T2 + col) = v;
            }
            if (r0 + 8 < NTOK) {
                float2 v = make_float2(acc2[mt][nt][2] + bv0, acc2[mt][nt][3] + bv1);
                *(float2*)(out + (b * NTOK + r0 + 8) * T2 + col) = v;
            }
        }
    }
}

extern "C" void kernel_launch(void* const* d_in, const int* in_sizes, int n_in,
                              void* d_out, int out_size) {
    const float* x  = (const float*)d_in[0];
    const float* rw = (const float*)d_in[1];
    const float* rb = (const float*)d_in[2];
    const float* w1 = (const float*)d_in[3];
    const float* b1 = (const float*)d_in[4];
    const float* w2 = (const float*)d_in[5];
    const float* b2 = (const float*)d_in[6];
    float* out = (float*)d_out;

    prep_w<<<dim3(104, 1, EE), dim3(32, 8)>>>(w1, w2, x, rw, rb);

    cudaFuncSetAttribute(moe_kernel, cudaFuncAttributeMaxDynamicSharedMemorySize, SM_TOT);
    moe_kernel<<<BB, 256, SM_TOT>>>(x, b1, b2, out);
}

// round 15
// speedup vs baseline: 1.4649x; 1.4649x over previous
#include <cuda_runtime.h>
#include <cuda_fp16.h>
#include <cstdint>

#define BB 256
#define NTOK 63
#define DD 128
#define EE 8
#define HH 256
#define T2 160

// ---------------- device globals ----------------
__device__ float g_gates[BB * 2];
__device__ int   g_eidx[BB * 2];
__device__ __half W1T[EE * HH * DD];     // [e][hcol][d] k-contig, fp16
__device__ __half W2T[EE * 4 * T2 * 64]; // [e][kchunk][o][64], fp16

// ---------------- smem layout (bytes) ----------------
#define SM_X    0                     // x: 64 rows x 256B (swz)
#define SM_H    16384                 // h: 2 bufs x 8192 (64 rows x 128B, swz)
#define SM_B1   32768                 // W1 chunk: 2 bufs x 16384 (swz)
#define SM_B2   65536                 // W2 chunk: 2 bufs x 20480 (160 rows x 128B, swz)
#define B2SZ    20480
#define SM_BIAS 106496                // 160 floats (combined out bias)
#define SM_BIAS1 107136               // 512 floats (b1 for e0,e1)
#define SM_TOT  109184

// named barrier ids
#define BAR_FULL0 1
#define BAR_FULL1 2
#define BAR_FREE0 3
#define BAR_FREE1 4
#define BAR_CONS  5
#define BAR_PROD  6

// ---------------- PTX helpers ----------------
__device__ __forceinline__ uint32_t smem_u32(const void* p) {
    uint32_t a;
    asm("{ .reg .u64 t; cvta.to.shared.u64 t, %1; cvt.u32.u64 %0, t; }" : "=r"(a) : "l"(p));
    return a;
}
__device__ __forceinline__ void ldsm4(uint32_t* r, uint32_t addr) {
    asm volatile("ldmatrix.sync.aligned.m8n8.x4.shared.b16 {%0,%1,%2,%3}, [%4];"
        : "=r"(r[0]), "=r"(r[1]), "=r"(r[2]), "=r"(r[3]) : "r"(addr));
}
__device__ __forceinline__ void ldsm2(uint32_t* r, uint32_t addr) {
    asm volatile("ldmatrix.sync.aligned.m8n8.x2.shared.b16 {%0,%1}, [%2];"
        : "=r"(r[0]), "=r"(r[1]) : "r"(addr));
}
__device__ __forceinline__ void mma16(float* d, const uint32_t* a, uint32_t b0, uint32_t b1) {
    asm volatile("mma.sync.aligned.m16n8k16.row.col.f32.f16.f16.f32 "
        "{%0,%1,%2,%3}, {%4,%5,%6,%7}, {%8,%9}, {%0,%1,%2,%3};"
        : "+f"(d[0]), "+f"(d[1]), "+f"(d[2]), "+f"(d[3])
        : "r"(a[0]), "r"(a[1]), "r"(a[2]), "r"(a[3]), "r"(b0), "r"(b1));
}
__device__ __forceinline__ void cp16(uint32_t dst, const void* src) {
    asm volatile("cp.async.cg.shared.global [%0], [%1], 16;" :: "r"(dst), "l"(src));
}
#define CP_COMMIT() asm volatile("cp.async.commit_group;" ::: "memory")
#define CP_WAIT(n)  asm volatile("cp.async.wait_group %0;" :: "n"(n) : "memory")
#define NBAR_SYNC(id, n)   asm volatile("bar.sync %0, %1;"   :: "r"(id), "r"(n) : "memory")
#define NBAR_ARRIVE(id, n) asm volatile("bar.arrive %0, %1;" :: "r"(id), "r"(n) : "memory")

// ---------------- prep: transpose + fp16 convert + fused router ----------------
__global__ void prep_w(const float* __restrict__ w1, const float* __restrict__ w2,
                       const float* __restrict__ x,  const float* __restrict__ rw,
                       const float* __restrict__ rb) {
    __shared__ float t[32][33];
    __shared__ float pooled[DD];
    __shared__ float logits[EE];
    int e = blockIdx.z, bx = blockIdx.x;
    int tx = threadIdx.x, ty = threadIdx.y;
    int tid = ty * 32 + tx;
    if (bx < 32) {
        int d0 = (bx & 3) * 32, h0 = (bx >> 2) * 32;
        #pragma unroll
        for (int i = 0; i < 4; i++)
            t[ty + 8 * i][tx] = w1[(e * DD + d0 + ty + 8 * i) * HH + h0 + tx];
        __syncthreads();
        #pragma unroll
        for (int i = 0; i < 4; i++)
            W1T[(e * HH + h0 + ty + 8 * i) * DD + d0 + tx] =
                __float2half_rn(t[tx][ty + 8 * i]);
    } else if (bx < 72) {
        int i2 = bx - 32;
        int k0 = (i2 & 7) * 32, o0 = (i2 >> 3) * 32;
        #pragma unroll
        for (int i = 0; i < 4; i++)
            t[ty + 8 * i][tx] = w2[(e * HH + k0 + ty + 8 * i) * T2 + o0 + tx];
        __syncthreads();
        #pragma unroll
        for (int i = 0; i < 4; i++) {
            int hd = k0 + tx, o = o0 + ty + 8 * i;
            W2T[((e * 4 + (hd >> 6)) * T2 + o) * 64 + (hd & 63)] =
                __float2half_rn(t[tx][ty + 8 * i]);
        }
    } else {
        int b = (bx - 72) * 8 + e;
        const float* xb = x + b * 64 * DD;
        if (tid < DD) {
            float s = 0.f;
            #pragma unroll 4
            for (int n = 1; n < 64; n++) s += xb[n * DD + tid];
            pooled[tid] = s * (1.0f / 63.0f);
        }
        __syncthreads();
        if (tid < EE) {
            float l = rb[tid];
            #pragma unroll 4
            for (int dd = 0; dd < DD; dd++) l += pooled[dd] * rw[dd * EE + tid];
            logits[tid] = l;
        }
        __syncthreads();
        if (tid == 0) {
            float mx = logits[0];
            #pragma unroll
            for (int k = 1; k < EE; k++) mx = fmaxf(mx, logits[k]);
            float p[EE];
            float se = 0.f;
            #pragma unroll
            for (int k = 0; k < EE; k++) { p[k] = expf(logits[k] - mx); se += p[k]; }
            int i1 = 0;
            #pragma unroll
            for (int k = 1; k < EE; k++) if (p[k] > p[i1]) i1 = k;
            int i2 = (i1 == 0) ? 1 : 0;
            #pragma unroll
            for (int k = 0; k < EE; k++) if (k != i1 && p[k] > p[i2]) i2 = k;
            float inv = 1.f / se;
            g_eidx[b * 2 + 0]  = i1;
            g_gates[b * 2 + 0] = p[i1] * inv;
            g_eidx[b * 2 + 1]  = i2;
            g_gates[b * 2 + 1] = p[i2] * inv;
        }
    }
}

// ---------------- cp.async loaders: per-group (128 threads), empty when over-range ----------------
__device__ __forceinline__ void load_b1t(uint32_t sb, int ch, int e0, int e1, int gt) {
    if (ch >= 8) return;
    int e = (ch >> 2) ? e1 : e0;
    const char* s = (const char*)(W1T + (e * HH + (ch & 3) * 64) * DD);
    uint32_t dst = sb + SM_B1 + (uint32_t)(ch & 1) * 16384;
    #pragma unroll
    for (int i = 0; i < 8; i++) {
        int c = gt + i * 128;     // 1024 copies over 128 threads
        int row = c >> 4, seg = c & 15;
        uint32_t d = (uint32_t)row * 256 + (uint32_t)((seg ^ (row & 7)) << 4);
        cp16(dst + d, s + c * 16);
    }
}
__device__ __forceinline__ void load_b2t(uint32_t sb, int ch, int e0, int e1, int gt) {
    if (ch >= 8) return;
    int e = (ch >> 2) ? e1 : e0;
    const char* s = (const char*)(W2T + (e * 4 + (ch & 3)) * T2 * 64);
    uint32_t buf = sb + SM_B2 + (uint32_t)(ch & 1) * B2SZ;
    #pragma unroll
    for (int i = 0; i < 10; i++) {
        int c = gt + i * 128;     // 1280 copies over 128 threads
        int row = c >> 3, seg = c & 7;
        uint32_t d = (uint32_t)row * 128 + (uint32_t)((seg ^ (row & 7)) << 4);
        cp16(buf + d, s + row * 128 + seg * 16);
    }
}

// ---------------- main fused kernel: warp-specialized producer/consumer ----------------
__global__ __launch_bounds__(256, 2) void moe_kernel(
    const float* __restrict__ x,
    const float* __restrict__ b1g,
    const float* __restrict__ b2g,
    float* __restrict__ out) {
    extern __shared__ char smem[];
    uint32_t sb = smem_u32(smem);
    int tid = threadIdx.x, wid = tid >> 5, lane = tid & 31;
    int b = blockIdx.x;
    const int t = lane >> 3, r8 = lane & 7, q = lane >> 2, p2 = (lane & 3) * 2;

    const int e0 = g_eidx[b * 2 + 0], e1 = g_eidx[b * 2 + 1];
    const float gt0 = g_gates[b * 2 + 0], gt1 = g_gates[b * 2 + 1];

    if (tid < T2)
        ((float*)(smem + SM_BIAS))[tid] =
            gt0 * __ldg(b2g + e0 * T2 + tid) + gt1 * __ldg(b2g + e1 * T2 + tid);
    {
        float* bc1 = (float*)(smem + SM_BIAS1);
        bc1[tid]       = __ldg(b1g + e0 * HH + tid);
        bc1[256 + tid] = __ldg(b1g + e1 * HH + tid);
    }
    // zero x row 63
    if (tid < 16) {
        uint32_t off = 63u * 256 + (uint32_t)((tid ^ 7) << 4);
        *(uint4*)(smem + SM_X + off) = make_uint4(0, 0, 0, 0);
    }
    // fill x rows 0..62, fp16, swizzled
    if (tid < 252) {
        int r = tid >> 2, seg32 = (tid & 3) * 32;
        const float4* xr = (const float4*)(x + (b * 64 + 1 + r) * DD + seg32);
        #pragma unroll
        for (int j = 0; j < 8; j++) {
            float4 v = xr[j];
            int d = seg32 + j * 4;
            uint32_t off = (uint32_t)r * 256 + (uint32_t)((((d >> 3) ^ (r & 7)) << 4) + ((d * 2) & 15));
            *(__half2*)(smem + SM_X + off)     = __floats2half2_rn(v.x, v.y);
            *(__half2*)(smem + SM_X + off + 4) = __floats2half2_rn(v.z, v.w);
        }
    }
    __syncthreads();

    const float* bc1 = (const float*)(smem + SM_BIAS1);

    if (wid < 4) {
        // ================= PRODUCER: GEMM1, warps 0-3 =================
        const int gt = tid;                   // 0..127
        const int w = wid;                    // m-tile
        load_b1t(sb, 0, e0, e1, gt); CP_COMMIT();
        load_b1t(sb, 1, e0, e1, gt); CP_COMMIT();

        // cache x A-fragments (all 8 k16 steps)
        const int rA = w * 16 + (t & 1) * 8 + r8;
        const uint32_t xbase = sb + SM_X + (uint32_t)rA * 256;
        uint32_t xf[32];
        #pragma unroll
        for (int ks = 0; ks < 8; ks++) {
            uint32_t sa = (uint32_t)(((2 * ks + (t >> 1)) ^ r8) << 4);
            ldsm4(xf + 4 * ks, xbase + sa);
        }

        for (int ch = 0; ch < 8; ch++) {
            const float g  = (ch >> 2) ? gt1 : gt0;
            const int   c4 = ch & 3;
            const int   p  = ch & 1;

            CP_WAIT(1);                              // B1(ch) ready
            if (ch >= 2) NBAR_SYNC(p ? BAR_FREE1 : BAR_FREE0, 256);  // H[p] free

            float acc1[8][4];
            #pragma unroll
            for (int nt = 0; nt < 8; nt++)
                #pragma unroll
                for (int j = 0; j < 4; j++) acc1[nt][j] = 0.f;

            uint32_t b1base = sb + SM_B1 + (uint32_t)p * 16384;
            #pragma unroll
            for (int ks = 0; ks < 8; ks++) {
                #pragma unroll
                for (int nt16 = 0; nt16 < 4; nt16++) {
                    int rB = nt16 * 16 + (t >> 1) * 8 + r8;
                    uint32_t a = b1base + (uint32_t)rB * 256 +
                                 (uint32_t)(((2 * ks + (t & 1)) ^ (rB & 7)) << 4);
                    uint32_t bh[4];
                    ldsm4(bh, a);
                    mma16(acc1[nt16 * 2],     xf + 4 * ks, bh[0], bh[1]);
                    mma16(acc1[nt16 * 2 + 1], xf + 4 * ks, bh[2], bh[3]);
                }
            }
            // h epilogue: bias + relu + gate -> fp16 into H[p]
            char* hbuf = smem + SM_H + p * 8192;
            #pragma unroll
            for (int nt = 0; nt < 8; nt++) {
                int col = nt * 8 + p2;
                float bv0 = bc1[(ch >> 2) * 256 + c4 * 64 + col];
                float bv1 = bc1[(ch >> 2) * 256 + c4 * 64 + col + 1];
                int r0 = w * 16 + q, r1 = r0 + 8;
                float v00 = g * fmaxf(acc1[nt][0] + bv0, 0.f);
                float v01 = g * fmaxf(acc1[nt][1] + bv1, 0.f);
                float v10 = g * fmaxf(acc1[nt][2] + bv0, 0.f);
                float v11 = g * fmaxf(acc1[nt][3] + bv1, 0.f);
                uint32_t o0 = (uint32_t)r0 * 128 + (uint32_t)((((col >> 3) ^ (r0 & 7)) << 4) + ((col * 2) & 15));
                uint32_t o1 = (uint32_t)r1 * 128 + (uint32_t)((((col >> 3) ^ (r1 & 7)) << 4) + ((col * 2) & 15));
                *(__half2*)(hbuf + o0) = __floats2half2_rn(v00, v01);
                *(__half2*)(hbuf + o1) = __floats2half2_rn(v10, v11);
            }
            NBAR_ARRIVE(p ? BAR_FULL1 : BAR_FULL0, 256);   // H[p] ready
            NBAR_SYNC(BAR_PROD, 128);                      // all producers done with B1 buf
            load_b1t(sb, ch + 2, e0, e1, gt); CP_COMMIT();
        }
    } else {
        // ================= CONSUMER: GEMM2, warps 4-7 =================
        const int gt = tid - 128;             // 0..127
        const int c = wid - 4;                // n-tile (40 cols)
        load_b2t(sb, 0, e0, e1, gt); CP_COMMIT();
        load_b2t(sb, 1, e0, e1, gt); CP_COMMIT();

        const int rW = c * 40 + (t >> 1) * 8 + r8;
        const int rX = c * 40 + 32 + r8;

        float acc2[4][5][4];
        #pragma unroll
        for (int mt = 0; mt < 4; mt++)
            #pragma unroll
            for (int nt = 0; nt < 5; nt++)
                #pragma unroll
                for (int j = 0; j < 4; j++) acc2[mt][nt][j] = 0.f;

        for (int ch = 0; ch < 8; ch++) {
            const int p = ch & 1;
            CP_WAIT(1);                                    // B2(ch) ready
            NBAR_SYNC(p ? BAR_FULL1 : BAR_FULL0, 256);     // H[p] ready

            uint32_t b2base = sb + SM_B2 + (uint32_t)p * B2SZ;
            uint32_t hb = sb + SM_H + (uint32_t)p * 8192;
            #pragma unroll
            for (int kt = 0; kt < 4; kt++) {
                uint32_t bseg = (uint32_t)(((kt * 2 + (t & 1)) ^ r8) << 4);
                uint32_t b01[4], b23[4], b4[2];
                ldsm4(b01, b2base + (uint32_t)rW * 128 + bseg);
                ldsm4(b23, b2base + (uint32_t)(rW + 16) * 128 + bseg);
                ldsm2(b4,  b2base + (uint32_t)rX * 128 + (uint32_t)(((kt * 2 + t) ^ r8) << 4));
                uint32_t sa = (uint32_t)(((kt * 2 + (t >> 1)) ^ r8) << 4);
                #pragma unroll
                for (int mt = 0; mt < 4; mt++) {
                    uint32_t ah[4];
                    ldsm4(ah, hb + (uint32_t)(mt * 16 + (t & 1) * 8 + r8) * 128 + sa);
                    mma16(acc2[mt][0], ah, b01[0], b01[1]);
                    mma16(acc2[mt][1], ah, b01[2], b01[3]);
                    mma16(acc2[mt][2], ah, b23[0], b23[1]);
                    mma16(acc2[mt][3], ah, b23[2], b23[3]);
                    mma16(acc2[mt][4], ah, b4[0], b4[1]);
                }
            }
            if (ch < 6) NBAR_ARRIVE(p ? BAR_FREE1 : BAR_FREE0, 256);  // H[p] free
            NBAR_SYNC(BAR_CONS, 128);                      // all consumers done with B2 buf
            load_b2t(sb, ch + 2, e0, e1, gt); CP_COMMIT();
        }

        // ---- final epilogue: combined bias + store ----
        const float* bc = (const float*)(smem + SM_BIAS);
        #pragma unroll
        for (int mt = 0; mt < 4; mt++) {
            int r0 = mt * 16 + q;
            #pragma unroll
            for (int nt = 0; nt < 5; nt++) {
                int col = c * 40 + nt * 8 + p2;
                float bv0 = bc[col], bv1 = bc[col + 1];
                if (r0 < NTOK) {
                    float2 v = make_float2(acc2[mt][nt][0] + bv0, acc2[mt][nt][1] + bv1);
                    *(float2*)(out + (b * NTOK + r0) * T2 + col) = v;
                }
                if (r0 + 8 < NTOK) {
                    float2 v = make_float2(acc2[mt][nt][2] + bv0, acc2[mt][nt][3] + bv1);
                    *(float2*)(out + (b * NTOK + r0 + 8) * T2 + col) = v;
                }
            }
        }
    }
}

extern "C" void kernel_launch(void* const* d_in, const int* in_sizes, int n_in,
                              void* d_out, int out_size) {
    const float* x  = (const float*)d_in[0];
    const float* rw = (const float*)d_in[1];
    const float* rb = (const float*)d_in[2];
    const float* w1 = (const float*)d_in[3];
    const float* b1 = (const float*)d_in[4];
    const float* w2 = (const float*)d_in[5];
    const float* b2 = (const float*)d_in[6];
    float* out = (float*)d_out;

    prep_w<<<dim3(104, 1, EE), dim3(32, 8)>>>(w1, w2, x, rw, rb);

    cudaFuncSetAttribute(moe_kernel, cudaFuncAttributeMaxDynamicSharedMemorySize, SM_TOT);
    moe_kernel<<<BB, 256, SM_TOT>>>(x, b1, b2, out);
}

// round 16
// speedup vs baseline: 1.4911x; 1.0179x over previous
#include <cuda_runtime.h>
#include <cuda_fp16.h>
#include <cstdint>

#define BB 256
#define NTOK 63
#define DD 128
#define EE 8
#define HH 256
#define T2 160

// ---------------- device globals ----------------
__device__ float g_gates[BB * 2];
__device__ int   g_eidx[BB * 2];
__device__ __half W1T[EE * HH * DD];     // [e][hcol][d] k-contig, fp16
__device__ __half W2T[EE * 4 * T2 * 64]; // [e][kchunk][o][64], fp16

// ---------------- smem layout (bytes) ----------------
#define SM_X    0                     // x: 64 rows x 256B (swz)
#define SM_H    16384                 // h chunk: 64 rows x 128B (swz)
#define SM_B1   24576                 // W1 chunk: 2 bufs x 16384 (swz)
#define SM_B2   57344                 // W2 chunk: 2 bufs x 20480 (160 rows x 128B, swz)
#define B2SZ    20480
#define SM_BIAS 98304                 // 160 floats (combined out bias)
#define SM_BIAS1 98944                // 512 floats (b1 for e0,e1)
#define SM_TOT  100992

// ---------------- PTX helpers ----------------
__device__ __forceinline__ uint32_t smem_u32(const void* p) {
    uint32_t a;
    asm("{ .reg .u64 t; cvta.to.shared.u64 t, %1; cvt.u32.u64 %0, t; }" : "=r"(a) : "l"(p));
    return a;
}
__device__ __forceinline__ void ldsm4(uint32_t* r, uint32_t addr) {
    asm volatile("ldmatrix.sync.aligned.m8n8.x4.shared.b16 {%0,%1,%2,%3}, [%4];"
        : "=r"(r[0]), "=r"(r[1]), "=r"(r[2]), "=r"(r[3]) : "r"(addr));
}
__device__ __forceinline__ void ldsm2(uint32_t* r, uint32_t addr) {
    asm volatile("ldmatrix.sync.aligned.m8n8.x2.shared.b16 {%0,%1}, [%2];"
        : "=r"(r[0]), "=r"(r[1]) : "r"(addr));
}
__device__ __forceinline__ void mma16(float* d, const uint32_t* a, uint32_t b0, uint32_t b1) {
    asm volatile("mma.sync.aligned.m16n8k16.row.col.f32.f16.f16.f32 "
        "{%0,%1,%2,%3}, {%4,%5,%6,%7}, {%8,%9}, {%0,%1,%2,%3};"
        : "+f"(d[0]), "+f"(d[1]), "+f"(d[2]), "+f"(d[3])
        : "r"(a[0]), "r"(a[1]), "r"(a[2]), "r"(a[3]), "r"(b0), "r"(b1));
}
__device__ __forceinline__ void cp16(uint32_t dst, const void* src) {
    asm volatile("cp.async.cg.shared.global [%0], [%1], 16;" :: "r"(dst), "l"(src));
}
#define CP_COMMIT() asm volatile("cp.async.commit_group;" ::: "memory")
#define CP_WAIT(n)  asm volatile("cp.async.wait_group %0;" :: "n"(n) : "memory")

// ---------------- prep: double-buffered transpose + fp16 convert + router ----------------
// grid (45,1,8): bx<8 -> W1 strip (4 tiles), bx<13 -> W2 strip (8 tiles), else router.
__global__ void prep_w(const float* __restrict__ w1, const float* __restrict__ w2,
                       const float* __restrict__ x,  const float* __restrict__ rw,
                       const float* __restrict__ rb) {
    __shared__ float t[2][32][33];
    __shared__ float part[2][DD];
    __shared__ float pooled[DD];
    __shared__ float logits[EE];
    int e = blockIdx.z, bx = blockIdx.x;
    int tid = threadIdx.y * 32 + threadIdx.x;
    int row = tid >> 3, c4 = tid & 7;     // load mapping
    int orow = tid >> 3, q4 = tid & 7;    // store mapping

    if (bx < 8) {
        // W1 strip: h0 fixed, 4 d-tiles, double-buffered
        int h0 = bx * 32;
        {
            float4 v = *(const float4*)(w1 + (e * DD + row) * HH + h0 + c4 * 4);
            t[0][row][c4 * 4 + 0] = v.x; t[0][row][c4 * 4 + 1] = v.y;
            t[0][row][c4 * 4 + 2] = v.z; t[0][row][c4 * 4 + 3] = v.w;
        }
        #pragma unroll
        for (int k = 0; k < 4; k++) {
            __syncthreads();
            if (k < 3) {
                float4 v = *(const float4*)(w1 + (e * DD + (k + 1) * 32 + row) * HH + h0 + c4 * 4);
                int nb = (k + 1) & 1;
                t[nb][row][c4 * 4 + 0] = v.x; t[nb][row][c4 * 4 + 1] = v.y;
                t[nb][row][c4 * 4 + 2] = v.z; t[nb][row][c4 * 4 + 3] = v.w;
            }
            int cb = k & 1;
            __half2 a = __floats2half2_rn(t[cb][q4 * 4 + 0][orow], t[cb][q4 * 4 + 1][orow]);
            __half2 bq = __floats2half2_rn(t[cb][q4 * 4 + 2][orow], t[cb][q4 * 4 + 3][orow]);
            uint2 pk = make_uint2(*(uint32_t*)&a, *(uint32_t*)&bq);
            *(uint2*)(W1T + (e * HH + h0 + orow) * DD + k * 32 + q4 * 4) = pk;
        }
    } else if (bx < 13) {
        // W2 strip: o0 fixed, 8 k-tiles, double-buffered
        int o0 = (bx - 8) * 32;
        {
            float4 v = *(const float4*)(w2 + (e * HH + row) * T2 + o0 + c4 * 4);
            t[0][row][c4 * 4 + 0] = v.x; t[0][row][c4 * 4 + 1] = v.y;
            t[0][row][c4 * 4 + 2] = v.z; t[0][row][c4 * 4 + 3] = v.w;
        }
        #pragma unroll
        for (int k = 0; k < 8; k++) {
            __syncthreads();
            if (k < 7) {
                float4 v = *(const float4*)(w2 + (e * HH + (k + 1) * 32 + row) * T2 + o0 + c4 * 4);
                int nb = (k + 1) & 1;
                t[nb][row][c4 * 4 + 0] = v.x; t[nb][row][c4 * 4 + 1] = v.y;
                t[nb][row][c4 * 4 + 2] = v.z; t[nb][row][c4 * 4 + 3] = v.w;
            }
            int cb = k & 1;
            int k0 = k * 32;
            __half2 a = __floats2half2_rn(t[cb][q4 * 4 + 0][orow], t[cb][q4 * 4 + 1][orow]);
            __half2 bq = __floats2half2_rn(t[cb][q4 * 4 + 2][orow], t[cb][q4 * 4 + 3][orow]);
            uint2 pk = make_uint2(*(uint32_t*)&a, *(uint32_t*)&bq);
            *(uint2*)(W2T + ((e * 4 + (k0 >> 6)) * T2 + o0 + orow) * 64 + (k0 & 63) + q4 * 4) = pk;
        }
    } else {
        // router for batch b, pooling split over 256 threads
        int b = (bx - 13) * 8 + e;
        const float* xb = x + b * 64 * DD;
        {
            int d = tid & 127, hf = tid >> 7;
            int n0 = hf ? 32 : 1, n1 = hf ? 64 : 32;
            float s = 0.f;
            #pragma unroll 4
            for (int n = n0; n < n1; n++) s += xb[n * DD + d];
            part[hf][d] = s;
        }
        __syncthreads();
        if (tid < DD) pooled[tid] = (part[0][tid] + part[1][tid]) * (1.0f / 63.0f);
        __syncthreads();
        if (tid < EE) {
            float l = rb[tid];
            #pragma unroll 4
            for (int dd = 0; dd < DD; dd++) l += pooled[dd] * rw[dd * EE + tid];
            logits[tid] = l;
        }
        __syncthreads();
        if (tid == 0) {
            float mx = logits[0];
            #pragma unroll
            for (int k = 1; k < EE; k++) mx = fmaxf(mx, logits[k]);
            float p[EE];
            float se = 0.f;
            #pragma unroll
            for (int k = 0; k < EE; k++) { p[k] = expf(logits[k] - mx); se += p[k]; }
            int i1 = 0;
            #pragma unroll
            for (int k = 1; k < EE; k++) if (p[k] > p[i1]) i1 = k;
            int i2 = (i1 == 0) ? 1 : 0;
            #pragma unroll
            for (int k = 0; k < EE; k++) if (k != i1 && p[k] > p[i2]) i2 = k;
            float inv = 1.f / se;
            g_eidx[b * 2 + 0]  = i1;
            g_gates[b * 2 + 0] = p[i1] * inv;
            g_eidx[b * 2 + 1]  = i2;
            g_gates[b * 2 + 1] = p[i2] * inv;
        }
    }
}

// ---------------- cp.async tile loaders (over-range calls are empty) ----------------
__device__ __forceinline__ void load_b1t(uint32_t sb, int ch, int e0, int e1, int tid) {
    if (ch >= 8) return;
    int e = (ch >> 2) ? e1 : e0;
    const char* s = (const char*)(W1T + (e * HH + (ch & 3) * 64) * DD);
    uint32_t dst = sb + SM_B1 + (uint32_t)(ch & 1) * 16384;
    #pragma unroll
    for (int i = 0; i < 4; i++) {
        int c = tid + i * 256;
        int row = c >> 4, seg = c & 15;
        uint32_t d = (uint32_t)row * 256 + (uint32_t)((seg ^ (row & 7)) << 4);
        cp16(dst + d, s + c * 16);
    }
}
__device__ __forceinline__ void load_b2t(uint32_t sb, int ch, int e0, int e1, int tid) {
    if (ch >= 8) return;
    int e = (ch >> 2) ? e1 : e0;
    const char* s = (const char*)(W2T + (e * 4 + (ch & 3)) * T2 * 64);
    uint32_t buf = sb + SM_B2 + (uint32_t)(ch & 1) * B2SZ;
    #pragma unroll
    for (int i = 0; i < 5; i++) {
        int c = tid + i * 256;
        int row = c >> 3, seg = c & 7;
        uint32_t d = (uint32_t)row * 128 + (uint32_t)((seg ^ (row & 7)) << 4);
        cp16(buf + d, s + row * 128 + seg * 16);
    }
}

// ---------------- main fused kernel (round-12 structure, prologue reordered) ----------------
__global__ __launch_bounds__(256, 2) void moe_kernel(
    const float* __restrict__ x,
    const float* __restrict__ b1g,
    const float* __restrict__ b2g,
    float* __restrict__ out) {
    extern __shared__ char smem[];
    uint32_t sb = smem_u32(smem);
    int tid = threadIdx.x, wid = tid >> 5, lane = tid & 31;
    int b = blockIdx.x;
    const int wm = wid & 3, wn = wid >> 2;       // GEMM1 grid 4m x 2n
    const int wm2 = wid >> 2, wn2 = wid & 3;     // GEMM2 grid 2m x 4n
    const int t = lane >> 3, r8 = lane & 7, q = lane >> 2, p2 = (lane & 3) * 2;

    const int e0 = g_eidx[b * 2 + 0], e1 = g_eidx[b * 2 + 1];
    const float gt0 = g_gates[b * 2 + 0], gt1 = g_gates[b * 2 + 1];

    // ---- weight prefetch FIRST: overlaps the x-staging LDG latency below ----
    load_b1t(sb, 0, e0, e1, tid);  CP_COMMIT();
    load_b2t(sb, 0, e0, e1, tid);  CP_COMMIT();
    load_b1t(sb, 1, e0, e1, tid);  CP_COMMIT();

    if (tid < T2)
        ((float*)(smem + SM_BIAS))[tid] =
            gt0 * __ldg(b2g + e0 * T2 + tid) + gt1 * __ldg(b2g + e1 * T2 + tid);
    {
        float* bc1w = (float*)(smem + SM_BIAS1);
        bc1w[tid]       = __ldg(b1g + e0 * HH + tid);
        bc1w[256 + tid] = __ldg(b1g + e1 * HH + tid);
    }
    // zero x row 63
    if (tid < 16) {
        uint32_t off = 63u * 256 + (uint32_t)((tid ^ 7) << 4);
        *(uint4*)(smem + SM_X + off) = make_uint4(0, 0, 0, 0);
    }
    // fill x rows 0..62, fp16, swizzled
    if (tid < 252) {
        int r = tid >> 2, seg32 = (tid & 3) * 32;
        const float4* xr = (const float4*)(x + (b * 64 + 1 + r) * DD + seg32);
        #pragma unroll
        for (int j = 0; j < 8; j++) {
            float4 v = xr[j];
            int d = seg32 + j * 4;
            uint32_t off = (uint32_t)r * 256 + (uint32_t)((((d >> 3) ^ (r & 7)) << 4) + ((d * 2) & 15));
            *(__half2*)(smem + SM_X + off)     = __floats2half2_rn(v.x, v.y);
            *(__half2*)(smem + SM_X + off + 4) = __floats2half2_rn(v.z, v.w);
        }
    }
    __syncthreads();

    // GEMM1 per-lane bases
    const int rA = wm * 16 + (t & 1) * 8 + r8;
    const uint32_t xbase = sb + SM_X + (uint32_t)rA * 256;
    const int rB0 = wn * 32 + (t >> 1) * 8 + r8;
    // GEMM2 per-lane bases
    const uint32_t hb2_0 = sb + SM_H + (uint32_t)(wm2 * 32 + (t & 1) * 8 + r8) * 128;
    const uint32_t hb2_1 = hb2_0 + 16 * 128;
    const int rW = wn2 * 40 + (t >> 1) * 8 + r8;
    const int rX = wn2 * 40 + 32 + r8;

    float acc2[2][5][4];
    #pragma unroll
    for (int mt = 0; mt < 2; mt++)
        #pragma unroll
        for (int nt = 0; nt < 5; nt++)
            #pragma unroll
            for (int j = 0; j < 4; j++) acc2[mt][nt][j] = 0.f;

    const float* bc1 = (const float*)(smem + SM_BIAS1);

    for (int ch = 0; ch < 8; ch++) {
        const float g  = (ch >> 2) ? gt1 : gt0;
        const int   c4 = ch & 3;

        // ---- sync#1: B1(ch) ready (oldest pending); H free ----
        CP_WAIT(2);
        __syncthreads();

        float acc1[4][4];
        #pragma unroll
        for (int nt = 0; nt < 4; nt++)
            #pragma unroll
            for (int j = 0; j < 4; j++) acc1[nt][j] = 0.f;

        uint32_t b1base = sb + SM_B1 + (uint32_t)(ch & 1) * 16384;
        #pragma unroll
        for (int ks = 0; ks < 8; ks++) {
            uint32_t ah[4];
            uint32_t sa = (uint32_t)(((2 * ks + (t >> 1)) ^ r8) << 4);
            ldsm4(ah, xbase + sa);
            #pragma unroll
            for (int ntp = 0; ntp < 2; ntp++) {
                int rB = rB0 + ntp * 16;
                uint32_t a = b1base + (uint32_t)rB * 256 +
                             (uint32_t)(((2 * ks + (t & 1)) ^ (rB & 7)) << 4);
                uint32_t bh[4];
                ldsm4(bh, a);
                mma16(acc1[ntp * 2],     ah, bh[0], bh[1]);
                mma16(acc1[ntp * 2 + 1], ah, bh[2], bh[3]);
            }
        }
        // h epilogue: bias + relu + gate -> fp16 (swizzled)
        #pragma unroll
        for (int nt = 0; nt < 4; nt++) {
            int col = wn * 32 + nt * 8 + p2;
            float bv0 = bc1[(ch >> 2) * 256 + c4 * 64 + col];
            float bv1 = bc1[(ch >> 2) * 256 + c4 * 64 + col + 1];
            int r0 = wm * 16 + q, r1 = r0 + 8;
            float v00 = g * fmaxf(acc1[nt][0] + bv0, 0.f);
            float v01 = g * fmaxf(acc1[nt][1] + bv1, 0.f);
            float v10 = g * fmaxf(acc1[nt][2] + bv0, 0.f);
            float v11 = g * fmaxf(acc1[nt][3] + bv1, 0.f);
            uint32_t o0 = (uint32_t)r0 * 128 + (uint32_t)((((col >> 3) ^ (r0 & 7)) << 4) + ((col * 2) & 15));
            uint32_t o1 = (uint32_t)r1 * 128 + (uint32_t)((((col >> 3) ^ (r1 & 7)) << 4) + ((col * 2) & 15));
            *(__half2*)(smem + SM_H + o0) = __floats2half2_rn(v00, v01);
            *(__half2*)(smem + SM_H + o1) = __floats2half2_rn(v10, v11);
        }

        // ---- sync#2: B2(ch) ready; H visible; buffers free for refill ----
        CP_WAIT(1);
        __syncthreads();
        load_b2t(sb, ch + 1, e0, e1, tid); CP_COMMIT();
        load_b1t(sb, ch + 2, e0, e1, tid); CP_COMMIT();

        // ---- GEMM2: full 64-k chunk, 2m x 4n warp tiles ----
        uint32_t b2base = sb + SM_B2 + (uint32_t)(ch & 1) * B2SZ;
        #pragma unroll
        for (int kt = 0; kt < 4; kt++) {
            uint32_t sa = (uint32_t)(((kt * 2 + (t >> 1)) ^ r8) << 4);
            uint32_t ah0[4], ah1[4];
            ldsm4(ah0, hb2_0 + sa);
            ldsm4(ah1, hb2_1 + sa);
            uint32_t bseg = (uint32_t)(((kt * 2 + (t & 1)) ^ r8) << 4);
            uint32_t b01[4], b23[4], b4[2];
            ldsm4(b01, b2base + (uint32_t)rW * 128 + bseg);
            ldsm4(b23, b2base + (uint32_t)(rW + 16) * 128 + bseg);
            ldsm2(b4,  b2base + (uint32_t)rX * 128 + (uint32_t)(((kt * 2 + t) ^ r8) << 4));
            mma16(acc2[0][0], ah0, b01[0], b01[1]);
            mma16(acc2[1][0], ah1, b01[0], b01[1]);
            mma16(acc2[0][1], ah0, b01[2], b01[3]);
            mma16(acc2[1][1], ah1, b01[2], b01[3]);
            mma16(acc2[0][2], ah0, b23[0], b23[1]);
            mma16(acc2[1][2], ah1, b23[0], b23[1]);
            mma16(acc2[0][3], ah0, b23[2], b23[3]);
            mma16(acc2[1][3], ah1, b23[2], b23[3]);
            mma16(acc2[0][4], ah0, b4[0], b4[1]);
            mma16(acc2[1][4], ah1, b4[0], b4[1]);
        }
    }

    // ---- final epilogue: combined bias + store (GEMM2 grid indices) ----
    const float* bc = (const float*)(smem + SM_BIAS);
    #pragma unroll
    for (int mt = 0; mt < 2; mt++) {
        int r0 = wm2 * 32 + mt * 16 + q;
        #pragma unroll
        for (int nt = 0; nt < 5; nt++) {
            int col = wn2 * 40 + nt * 8 + p2;
            float bv0 = bc[col], bv1 = bc[col + 1];
            if (r0 < NTOK) {
                float2 v = make_float2(acc2[mt][nt][0] + bv0, acc2[mt][nt][1] + bv1);
                *(float2*)(out + (b * NTOK + r0) * T2 + col) = v;
            }
            if (r0 + 8 < NTOK) {
                float2 v = make_float2(acc2[mt][nt][2] + bv0, acc2[mt][nt][3] + bv1);
                *(float2*)(out + (b * NTOK + r0 + 8) * T2 + col) = v;
            }
        }
    }
}

extern "C" void kernel_launch(void* const* d_in, const int* in_sizes, int n_in,
                              void* d_out, int out_size) {
    const float* x  = (const float*)d_in[0];
    const float* rw = (const float*)d_in[1];
    const float* rb = (const float*)d_in[2];
    const float* w1 = (const float*)d_in[3];
    const float* b1 = (const float*)d_in[4];
    const float* w2 = (const float*)d_in[5];
    const float* b2 = (const float*)d_in[6];
    float* out = (float*)d_out;

    prep_w<<<dim3(45, 1, EE), dim3(32, 8)>>>(w1, w2, x, rw, rb);

    cudaFuncSetAttribute(moe_kernel, cudaFuncAttributeMaxDynamicSharedMemorySize, SM_TOT);
    moe_kernel<<<BB, 256, SM_TOT>>>(x, b1, b2, out);
}

// round 17
// speedup vs baseline: 1.5182x; 1.0182x over previous
#include <cuda_runtime.h>
#include <cuda_fp16.h>
#include <cstdint>

#define BB 256
#define NTOK 63
#define DD 128
#define EE 8
#define HH 256
#define T2 160

// ---------------- device globals ----------------
__device__ float g_gates[BB * 2];
__device__ int   g_eidx[BB * 2];
__device__ __half W1T[EE * HH * DD];     // [e][hcol][d] k-contig, fp16
__device__ __half W2T[EE * 4 * T2 * 64]; // [e][kchunk][o][64], fp16

// ---------------- smem layout (bytes) ----------------
#define SM_X    0                     // x: 64 rows x 256B (swz)
#define SM_H    16384                 // h: 2 bufs x 8192 (64 rows x 128B, swz)
#define SM_B1   32768                 // W1 chunk: 2 bufs x 16384 (swz)
#define SM_B2   65536                 // W2 half-chunks: 4 rotating bufs x 10240 (80 rows x 128B, swz)
#define B2HSZ   10240
#define SM_BIAS 106496                // 160 floats (combined out bias)
#define SM_BIAS1 107136               // 512 floats (b1 for e0,e1)
#define SM_TOT  109184

// ---------------- PTX helpers ----------------
__device__ __forceinline__ uint32_t smem_u32(const void* p) {
    uint32_t a;
    asm("{ .reg .u64 t; cvta.to.shared.u64 t, %1; cvt.u32.u64 %0, t; }" : "=r"(a) : "l"(p));
    return a;
}
__device__ __forceinline__ void ldsm4(uint32_t* r, uint32_t addr) {
    asm volatile("ldmatrix.sync.aligned.m8n8.x4.shared.b16 {%0,%1,%2,%3}, [%4];"
        : "=r"(r[0]), "=r"(r[1]), "=r"(r[2]), "=r"(r[3]) : "r"(addr));
}
__device__ __forceinline__ void ldsm2(uint32_t* r, uint32_t addr) {
    asm volatile("ldmatrix.sync.aligned.m8n8.x2.shared.b16 {%0,%1}, [%2];"
        : "=r"(r[0]), "=r"(r[1]) : "r"(addr));
}
__device__ __forceinline__ void mma16(float* d, const uint32_t* a, uint32_t b0, uint32_t b1) {
    asm volatile("mma.sync.aligned.m16n8k16.row.col.f32.f16.f16.f32 "
        "{%0,%1,%2,%3}, {%4,%5,%6,%7}, {%8,%9}, {%0,%1,%2,%3};"
        : "+f"(d[0]), "+f"(d[1]), "+f"(d[2]), "+f"(d[3])
        : "r"(a[0]), "r"(a[1]), "r"(a[2]), "r"(a[3]), "r"(b0), "r"(b1));
}
__device__ __forceinline__ void cp16(uint32_t dst, const void* src) {
    asm volatile("cp.async.cg.shared.global [%0], [%1], 16;" :: "r"(dst), "l"(src));
}
#define CP_COMMIT() asm volatile("cp.async.commit_group;" ::: "memory")
#define CP_WAIT(n)  asm volatile("cp.async.wait_group %0;" :: "n"(n) : "memory")

// ---------------- prep: double-buffered transpose + fp16 convert + router ----------------
__global__ void prep_w(const float* __restrict__ w1, const float* __restrict__ w2,
                       const float* __restrict__ x,  const float* __restrict__ rw,
                       const float* __restrict__ rb) {
    __shared__ float t[2][32][33];
    __shared__ float part[2][DD];
    __shared__ float pooled[DD];
    __shared__ float logits[EE];
    int e = blockIdx.z, bx = blockIdx.x;
    int tid = threadIdx.y * 32 + threadIdx.x;
    int row = tid >> 3, c4 = tid & 7;
    int orow = tid >> 3, q4 = tid & 7;

    if (bx < 8) {
        int h0 = bx * 32;
        {
            float4 v = *(const float4*)(w1 + (e * DD + row) * HH + h0 + c4 * 4);
            t[0][row][c4 * 4 + 0] = v.x; t[0][row][c4 * 4 + 1] = v.y;
            t[0][row][c4 * 4 + 2] = v.z; t[0][row][c4 * 4 + 3] = v.w;
        }
        #pragma unroll
        for (int k = 0; k < 4; k++) {
            __syncthreads();
            if (k < 3) {
                float4 v = *(const float4*)(w1 + (e * DD + (k + 1) * 32 + row) * HH + h0 + c4 * 4);
                int nb = (k + 1) & 1;
                t[nb][row][c4 * 4 + 0] = v.x; t[nb][row][c4 * 4 + 1] = v.y;
                t[nb][row][c4 * 4 + 2] = v.z; t[nb][row][c4 * 4 + 3] = v.w;
            }
            int cb = k & 1;
            __half2 a = __floats2half2_rn(t[cb][q4 * 4 + 0][orow], t[cb][q4 * 4 + 1][orow]);
            __half2 bq = __floats2half2_rn(t[cb][q4 * 4 + 2][orow], t[cb][q4 * 4 + 3][orow]);
            uint2 pk = make_uint2(*(uint32_t*)&a, *(uint32_t*)&bq);
            *(uint2*)(W1T + (e * HH + h0 + orow) * DD + k * 32 + q4 * 4) = pk;
        }
    } else if (bx < 13) {
        int o0 = (bx - 8) * 32;
        {
            float4 v = *(const float4*)(w2 + (e * HH + row) * T2 + o0 + c4 * 4);
            t[0][row][c4 * 4 + 0] = v.x; t[0][row][c4 * 4 + 1] = v.y;
            t[0][row][c4 * 4 + 2] = v.z; t[0][row][c4 * 4 + 3] = v.w;
        }
        #pragma unroll
        for (int k = 0; k < 8; k++) {
            __syncthreads();
            if (k < 7) {
                float4 v = *(const float4*)(w2 + (e * HH + (k + 1) * 32 + row) * T2 + o0 + c4 * 4);
                int nb = (k + 1) & 1;
                t[nb][row][c4 * 4 + 0] = v.x; t[nb][row][c4 * 4 + 1] = v.y;
                t[nb][row][c4 * 4 + 2] = v.z; t[nb][row][c4 * 4 + 3] = v.w;
            }
            int cb = k & 1;
            int k0 = k * 32;
            __half2 a = __floats2half2_rn(t[cb][q4 * 4 + 0][orow], t[cb][q4 * 4 + 1][orow]);
            __half2 bq = __floats2half2_rn(t[cb][q4 * 4 + 2][orow], t[cb][q4 * 4 + 3][orow]);
            uint2 pk = make_uint2(*(uint32_t*)&a, *(uint32_t*)&bq);
            *(uint2*)(W2T + ((e * 4 + (k0 >> 6)) * T2 + o0 + orow) * 64 + (k0 & 63) + q4 * 4) = pk;
        }
    } else {
        int b = (bx - 13) * 8 + e;
        const float* xb = x + b * 64 * DD;
        {
            int d = tid & 127, hf = tid >> 7;
            int n0 = hf ? 32 : 1, n1 = hf ? 64 : 32;
            float s = 0.f;
            #pragma unroll 4
            for (int n = n0; n < n1; n++) s += xb[n * DD + d];
            part[hf][d] = s;
        }
        __syncthreads();
        if (tid < DD) pooled[tid] = (part[0][tid] + part[1][tid]) * (1.0f / 63.0f);
        __syncthreads();
        if (tid < EE) {
            float l = rb[tid];
            #pragma unroll 4
            for (int dd = 0; dd < DD; dd++) l += pooled[dd] * rw[dd * EE + tid];
            logits[tid] = l;
        }
        __syncthreads();
        if (tid == 0) {
            float mx = logits[0];
            #pragma unroll
            for (int k = 1; k < EE; k++) mx = fmaxf(mx, logits[k]);
            float p[EE];
            float se = 0.f;
            #pragma unroll
            for (int k = 0; k < EE; k++) { p[k] = expf(logits[k] - mx); se += p[k]; }
            int i1 = 0;
            #pragma unroll
            for (int k = 1; k < EE; k++) if (p[k] > p[i1]) i1 = k;
            int i2 = (i1 == 0) ? 1 : 0;
            #pragma unroll
            for (int k = 0; k < EE; k++) if (k != i1 && p[k] > p[i2]) i2 = k;
            float inv = 1.f / se;
            g_eidx[b * 2 + 0]  = i1;
            g_gates[b * 2 + 0] = p[i1] * inv;
            g_eidx[b * 2 + 1]  = i2;
            g_gates[b * 2 + 1] = p[i2] * inv;
        }
    }
}

// ---------------- cp.async tile loaders (over-range calls are empty) ----------------
__device__ __forceinline__ void load_b1t(uint32_t sb, int ch, int e0, int e1, int tid) {
    if (ch >= 8) return;
    int e = (ch >> 2) ? e1 : e0;
    const char* s = (const char*)(W1T + (e * HH + (ch & 3) * 64) * DD);
    uint32_t dst = sb + SM_B1 + (uint32_t)(ch & 1) * 16384;
    #pragma unroll
    for (int i = 0; i < 4; i++) {
        int c = tid + i * 256;
        int row = c >> 4, seg = c & 15;
        uint32_t d = (uint32_t)row * 256 + (uint32_t)((seg ^ (row & 7)) << 4);
        cp16(dst + d, s + c * 16);
    }
}
// half-chunk of W2: o-rows [half*80, half*80+80), 64 k-cols (128B rows), buf (2ch+half)&3
__device__ __forceinline__ void load_b2h(uint32_t sb, int ch, int half, int e0, int e1, int tid) {
    if (ch >= 8) return;
    int e = (ch >> 2) ? e1 : e0;
    const char* s = (const char*)(W2T + ((e * 4 + (ch & 3)) * T2 + half * 80) * 64);
    uint32_t buf = sb + SM_B2 + (uint32_t)((2 * ch + half) & 3) * B2HSZ;
    #pragma unroll
    for (int i = 0; i < 3; i++) {
        int c = tid + i * 256;     // 640 copies
        if (c < 640) {
            int row = c >> 3, seg = c & 7;
            uint32_t d = (uint32_t)row * 128 + (uint32_t)((seg ^ (row & 7)) << 4);
            cp16(buf + d, s + row * 128 + seg * 16);
        }
    }
}

// ---------------- main fused kernel: 1 barrier/chunk, G2 lags G1 by one chunk ----------------
__global__ __launch_bounds__(256, 2) void moe_kernel(
    const float* __restrict__ x,
    const float* __restrict__ b1g,
    const float* __restrict__ b2g,
    float* __restrict__ out) {
    extern __shared__ char smem[];
    uint32_t sb = smem_u32(smem);
    int tid = threadIdx.x, wid = tid >> 5, lane = tid & 31;
    int b = blockIdx.x;
    const int wm = wid & 3, wn = wid >> 2;       // GEMM1 grid 4m x 2n
    const int wm2 = wid >> 2, wn2 = wid & 3;     // GEMM2 grid 2m x 4n
    const int t = lane >> 3, r8 = lane & 7, q = lane >> 2, p2 = (lane & 3) * 2;

    const int e0 = g_eidx[b * 2 + 0], e1 = g_eidx[b * 2 + 1];
    const float gt0 = g_gates[b * 2 + 0], gt1 = g_gates[b * 2 + 1];

    // prologue: B1(0) only (covered by x staging below)
    load_b1t(sb, 0, e0, e1, tid);  CP_COMMIT();

    if (tid < T2)
        ((float*)(smem + SM_BIAS))[tid] =
            gt0 * __ldg(b2g + e0 * T2 + tid) + gt1 * __ldg(b2g + e1 * T2 + tid);
    {
        float* bc1w = (float*)(smem + SM_BIAS1);
        bc1w[tid]       = __ldg(b1g + e0 * HH + tid);
        bc1w[256 + tid] = __ldg(b1g + e1 * HH + tid);
    }
    // zero x row 63
    if (tid < 16) {
        uint32_t off = 63u * 256 + (uint32_t)((tid ^ 7) << 4);
        *(uint4*)(smem + SM_X + off) = make_uint4(0, 0, 0, 0);
    }
    // fill x rows 0..62, fp16, swizzled
    if (tid < 252) {
        int r = tid >> 2, seg32 = (tid & 3) * 32;
        const float4* xr = (const float4*)(x + (b * 64 + 1 + r) * DD + seg32);
        #pragma unroll
        for (int j = 0; j < 8; j++) {
            float4 v = xr[j];
            int d = seg32 + j * 4;
            uint32_t off = (uint32_t)r * 256 + (uint32_t)((((d >> 3) ^ (r & 7)) << 4) + ((d * 2) & 15));
            *(__half2*)(smem + SM_X + off)     = __floats2half2_rn(v.x, v.y);
            *(__half2*)(smem + SM_X + off + 4) = __floats2half2_rn(v.z, v.w);
        }
    }
    __syncthreads();

    // GEMM1 per-lane bases
    const int rA = wm * 16 + (t & 1) * 8 + r8;
    const uint32_t xbase = sb + SM_X + (uint32_t)rA * 256;
    const int rB0 = wn * 32 + (t >> 1) * 8 + r8;
    // GEMM2 per-lane bases (o-local within the warp's half buffer)
    const int half2 = wn2 >> 1;
    const int rWl = (wn2 & 1) * 40 + (t >> 1) * 8 + r8;
    const int rXl = (wn2 & 1) * 40 + 32 + r8;

    float acc2[2][5][4];
    #pragma unroll
    for (int mt = 0; mt < 2; mt++)
        #pragma unroll
        for (int nt = 0; nt < 5; nt++)
            #pragma unroll
            for (int j = 0; j < 4; j++) acc2[mt][nt][j] = 0.f;

    const float* bc1 = (const float*)(smem + SM_BIAS1);

    for (int ch = 0; ch < 8; ch++) {
        const float g  = (ch >> 2) ? gt1 : gt0;
        const int   c4 = ch & 3;

        // ---- single sync: last iter's loads done; H/B bufs free per rotation proof ----
        CP_WAIT(0);
        __syncthreads();
        load_b2h(sb, ch, 0, e0, e1, tid); CP_COMMIT();
        load_b2h(sb, ch, 1, e0, e1, tid); CP_COMMIT();
        load_b1t(sb, ch + 1, e0, e1, tid); CP_COMMIT();

        // ---- G1(ch) into H[ch&1] ----
        {
            float acc1[4][4];
            #pragma unroll
            for (int nt = 0; nt < 4; nt++)
                #pragma unroll
                for (int j = 0; j < 4; j++) acc1[nt][j] = 0.f;

            uint32_t b1base = sb + SM_B1 + (uint32_t)(ch & 1) * 16384;
            #pragma unroll
            for (int ks = 0; ks < 8; ks++) {
                uint32_t ah[4];
                uint32_t sa = (uint32_t)(((2 * ks + (t >> 1)) ^ r8) << 4);
                ldsm4(ah, xbase + sa);
                #pragma unroll
                for (int ntp = 0; ntp < 2; ntp++) {
                    int rB = rB0 + ntp * 16;
                    uint32_t a = b1base + (uint32_t)rB * 256 +
                                 (uint32_t)(((2 * ks + (t & 1)) ^ (rB & 7)) << 4);
                    uint32_t bh[4];
                    ldsm4(bh, a);
                    mma16(acc1[ntp * 2],     ah, bh[0], bh[1]);
                    mma16(acc1[ntp * 2 + 1], ah, bh[2], bh[3]);
                }
            }
            char* hbuf = smem + SM_H + (ch & 1) * 8192;
            #pragma unroll
            for (int nt = 0; nt < 4; nt++) {
                int col = wn * 32 + nt * 8 + p2;
                float bv0 = bc1[(ch >> 2) * 256 + c4 * 64 + col];
                float bv1 = bc1[(ch >> 2) * 256 + c4 * 64 + col + 1];
                int r0 = wm * 16 + q, r1 = r0 + 8;
                float v00 = g * fmaxf(acc1[nt][0] + bv0, 0.f);
                float v01 = g * fmaxf(acc1[nt][1] + bv1, 0.f);
                float v10 = g * fmaxf(acc1[nt][2] + bv0, 0.f);
                float v11 = g * fmaxf(acc1[nt][3] + bv1, 0.f);
                uint32_t o0 = (uint32_t)r0 * 128 + (uint32_t)((((col >> 3) ^ (r0 & 7)) << 4) + ((col * 2) & 15));
                uint32_t o1 = (uint32_t)r1 * 128 + (uint32_t)((((col >> 3) ^ (r1 & 7)) << 4) + ((col * 2) & 15));
                *(__half2*)(hbuf + o0) = __floats2half2_rn(v00, v01);
                *(__half2*)(hbuf + o1) = __floats2half2_rn(v10, v11);
            }
        }

        // ---- G2(ch-1) from H[(ch-1)&1] and B2 bufs (2(ch-1)+half)&3 ----
        if (ch >= 1) {
            const int cc = ch - 1;
            uint32_t b2b = sb + SM_B2 + (uint32_t)((2 * cc + half2) & 3) * B2HSZ;
            uint32_t hb = sb + SM_H + (uint32_t)(cc & 1) * 8192;
            uint32_t hb0 = hb + (uint32_t)(wm2 * 32 + (t & 1) * 8 + r8) * 128;
            uint32_t hb1 = hb0 + 16 * 128;
            #pragma unroll
            for (int kt = 0; kt < 4; kt++) {
                uint32_t sa = (uint32_t)(((kt * 2 + (t >> 1)) ^ r8) << 4);
                uint32_t ah0[4], ah1[4];
                ldsm4(ah0, hb0 + sa);
                ldsm4(ah1, hb1 + sa);
                uint32_t bseg = (uint32_t)(((kt * 2 + (t & 1)) ^ r8) << 4);
                uint32_t b01[4], b23[4], b4[2];
                ldsm4(b01, b2b + (uint32_t)rWl * 128 + bseg);
                ldsm4(b23, b2b + (uint32_t)(rWl + 16) * 128 + bseg);
                ldsm2(b4,  b2b + (uint32_t)rXl * 128 + (uint32_t)(((kt * 2 + t) ^ r8) << 4));
                mma16(acc2[0][0], ah0, b01[0], b01[1]);
                mma16(acc2[1][0], ah1, b01[0], b01[1]);
                mma16(acc2[0][1], ah0, b01[2], b01[3]);
                mma16(acc2[1][1], ah1, b01[2], b01[3]);
                mma16(acc2[0][2], ah0, b23[0], b23[1]);
                mma16(acc2[1][2], ah1, b23[0], b23[1]);
                mma16(acc2[0][3], ah0, b23[2], b23[3]);
                mma16(acc2[1][3], ah1, b23[2], b23[3]);
                mma16(acc2[0][4], ah0, b4[0], b4[1]);
                mma16(acc2[1][4], ah1, b4[0], b4[1]);
            }
        }
    }

    // ---- tail: G2(7) ----
    CP_WAIT(0);
    __syncthreads();
    {
        const int cc = 7;
        uint32_t b2b = sb + SM_B2 + (uint32_t)((2 * cc + half2) & 3) * B2HSZ;
        uint32_t hb = sb + SM_H + (uint32_t)(cc & 1) * 8192;
        uint32_t hb0 = hb + (uint32_t)(wm2 * 32 + (t & 1) * 8 + r8) * 128;
        uint32_t hb1 = hb0 + 16 * 128;
        #pragma unroll
        for (int kt = 0; kt < 4; kt++) {
            uint32_t sa = (uint32_t)(((kt * 2 + (t >> 1)) ^ r8) << 4);
            uint32_t ah0[4], ah1[4];
            ldsm4(ah0, hb0 + sa);
            ldsm4(ah1, hb1 + sa);
            uint32_t bseg = (uint32_t)(((kt * 2 + (t & 1)) ^ r8) << 4);
            uint32_t b01[4], b23[4], b4[2];
            ldsm4(b01, b2b + (uint32_t)rWl * 128 + bseg);
            ldsm4(b23, b2b + (uint32_t)(rWl + 16) * 128 + bseg);
            ldsm2(b4,  b2b + (uint32_t)rXl * 128 + (uint32_t)(((kt * 2 + t) ^ r8) << 4));
            mma16(acc2[0][0], ah0, b01[0], b01[1]);
            mma16(acc2[1][0], ah1, b01[0], b01[1]);
            mma16(acc2[0][1], ah0, b01[2], b01[3]);
            mma16(acc2[1][1], ah1, b01[2], b01[3]);
            mma16(acc2[0][2], ah0, b23[0], b23[1]);
            mma16(acc2[1][2], ah1, b23[0], b23[1]);
            mma16(acc2[0][3], ah0, b23[2], b23[3]);
            mma16(acc2[1][3], ah1, b23[2], b23[3]);
            mma16(acc2[0][4], ah0, b4[0], b4[1]);
            mma16(acc2[1][4], ah1, b4[0], b4[1]);
        }
    }

    // ---- final epilogue: combined bias + store (GEMM2 grid indices) ----
    const float* bc = (const float*)(smem + SM_BIAS);
    #pragma unroll
    for (int mt = 0; mt < 2; mt++) {
        int r0 = wm2 * 32 + mt * 16 + q;
        #pragma unroll
        for (int nt = 0; nt < 5; nt++) {
            int col = wn2 * 40 + nt * 8 + p2;
            float bv0 = bc[col], bv1 = bc[col + 1];
            if (r0 < NTOK) {
                float2 v = make_float2(acc2[mt][nt][0] + bv0, acc2[mt][nt][1] + bv1);
                *(float2*)(out + (b * NTOK + r0) * T2 + col) = v;
            }
            if (r0 + 8 < NTOK) {
                float2 v = make_float2(acc2[mt][nt][2] + bv0, acc2[mt][nt][3] + bv1);
                *(float2*)(out + (b * NTOK + r0 + 8) * T2 + col) = v;
            }
        }
    }
}

extern "C" void kernel_launch(void* const* d_in, const int* in_sizes, int n_in,
                              void* d_out, int out_size) {
    const float* x  = (const float*)d_in[0];
    const float* rw = (const float*)d_in[1];
    const float* rb = (const float*)d_in[2];
    const float* w1 = (const float*)d_in[3];
    const float* b1 = (const float*)d_in[4];
    const float* w2 = (const float*)d_in[5];
    const float* b2 = (const float*)d_in[6];
    float* out = (float*)d_out;

    prep_w<<<dim3(45, 1, EE), dim3(32, 8)>>>(w1, w2, x, rw, rb);

    cudaFuncSetAttribute(moe_kernel, cudaFuncAttributeMaxDynamicSharedMemorySize, SM_TOT);
    moe_kernel<<<BB, 256, SM_TOT>>>(x, b1, b2, out);
}